// round 15
// baseline (speedup 1.0000x reference)
#include <cuda_runtime.h>
#include <cuda_fp16.h>
#include <cstdint>

#define BSZ 8
#define CH  64
#define H   256
#define W   256
#define HW  (H*W)
#define EPS 1e-5f
#define SLOPE 0.01f
#define CROP 244
#define CSPL 0.03125f   // c = 2^-5 split-compensation constant

typedef unsigned long long u64;

#define FMA2(d,a,b,c) asm("fma.rn.f32x2 %0, %1, %2, %3;" : "=l"(d) : "l"(a), "l"(b), "l"(c))
#define PACK2(d,lo,hi) asm("mov.b64 %0, {%1, %2};" : "=l"(d) : "f"(lo), "f"(hi))
#define UNPK2(lo,hi,d) asm("mov.b64 {%0, %1}, %2;" : "=f"(lo), "=f"(hi) : "l"(d))

__device__ __forceinline__ uint32_t smem_u32(const void* p) {
    uint32_t a;
    asm("{ .reg .u64 t; cvta.to.shared.u64 t, %1; cvt.u32.u64 %0, t; }" : "=r"(a) : "l"(p));
    return a;
}
__device__ __forceinline__ void ldsm4(uint32_t* r, uint32_t addr) {
    asm volatile("ldmatrix.sync.aligned.m8n8.x4.shared.b16 {%0,%1,%2,%3}, [%4];"
                 : "=r"(r[0]), "=r"(r[1]), "=r"(r[2]), "=r"(r[3]) : "r"(addr));
}
__device__ __forceinline__ void mma16816h(float* d, const uint32_t* a, const uint32_t* b) {
    asm volatile("mma.sync.aligned.m16n8k16.row.col.f32.f16.f16.f32 "
                 "{%0,%1,%2,%3}, {%4,%5,%6,%7}, {%8,%9}, {%0,%1,%2,%3};"
                 : "+f"(d[0]), "+f"(d[1]), "+f"(d[2]), "+f"(d[3])
                 : "r"(a[0]), "r"(a[1]), "r"(a[2]), "r"(a[3]), "r"(b[0]), "r"(b[1]));
}
__device__ __forceinline__ void cpasync16(uint32_t dst, const void* src) {
    asm volatile("cp.async.ca.shared.global [%0], [%1], 16;" :: "r"(dst), "l"(src));
}
#define CPASYNC_COMMIT() asm volatile("cp.async.commit_group;" ::: "memory")
#define CPASYNC_WAIT0()  asm volatile("cp.async.wait_group 0;" ::: "memory")

// ---------------- scratch ----------------
__device__ float g_actA[BSZ*CH*HW];
__device__ float g_actB[BSZ*CH*HW];
__device__ float g_stats[8*BSZ*CH*2];
__device__ float g_loss_part[BSZ*13*13*3];   // (X, S1hr, S2hr) per (b, sy, sx)
__device__ float g_loss_t[BSZ*2];            // (S1t, S2t) per b
// [layer][img(bh=0,b2=1)][tap][4096] fp16 ldmatrix-swizzled co x ci images (R12-proven layout)
__device__ __half g_wprep[7*2*9*4096];

// ---------------- weight prep: wh image + compensated w2 image (+ zero accums) ----------------
// image layout: byte_off = co*128 + (((ci>>3) ^ (co&7))<<4) + (ci&7)*2
__global__ void wprep_kernel(const float* __restrict__ ws) {
    const int t = blockIdx.x;    // tap 0..8
    const int l = blockIdx.y;    // layer 0..6
    if (t == 0 && l == 0) {      // fold accumulator zeroing into this launch
        for (int i = threadIdx.x; i < 8*BSZ*CH*2; i += blockDim.x) g_stats[i] = 0.f;
        for (int i = threadIdx.x; i < BSZ*13*13*3; i += blockDim.x) g_loss_part[i] = 0.f;
        if (threadIdx.x < BSZ*2) g_loss_t[threadIdx.x] = 0.f;
    }
    char* dst0 = (char*)(g_wprep + ((size_t)l*18 +     t)*4096);   // bh
    char* dst1 = (char*)(g_wprep + ((size_t)l*18 + 9 + t)*4096);   // b2
    for (int g = threadIdx.x; g < 4096; g += blockDim.x) {
        int co = g >> 6, ci = g & 63;
        float w = ws[(((size_t)l*64 + co)*64 + ci)*9 + t];
        __half wh = __float2half_rn(w);
        float whf = __half2float(wh);
        __half w2 = __float2half_rn(whf + 32.0f*(w - whf));   // wh + wl/c
        uint32_t off = (uint32_t)co*128 + ((((uint32_t)ci >> 3) ^ (co & 7)) << 4) + (ci & 7)*2;
        *(__half*)(dst0 + off) = wh;
        *(__half*)(dst1 + off) = w2;
    }
}

// ---------------- HMMA conv layer: M256 tile, sequential compensated 2-pass ----------------
// smem: window xh [340*128B], window a2 [340*128B], B dbl [2*8KB], nrm [512B]
#define OF_WHI 0
#define OF_WLO 43520
#define OF_B   87040
#define OF_NRM 103424
#define SMEM_MMA 103936
#define EPI_STRIDE 264

__global__ void __launch_bounds__(256, 2)
mma_conv_kernel(const float* __restrict__ in,
                const __half* __restrict__ wp,          // this layer: [2][9][4096]
                const float* __restrict__ bias,
                const float* __restrict__ rawst,        // [BSZ*64*2] raw (sum, sumsq) of input
                float* __restrict__ out,
                float* __restrict__ statacc)            // [BSZ*64*2] raw accum for output
{
    extern __shared__ char smem[];
    const uint32_t sb = smem_u32(smem);
    const int tid = threadIdx.x;
    const int wid = tid >> 5, lane = tid & 31;
    const int tileW = blockIdx.x;   // 0..7   (32 w)
    const int tileH = blockIdx.y;   // 0..31  (8 h)
    const int b = blockIdx.z;

    // folded finalize: raw (sum, sumsq) -> (mean, rstd)
    if (tid < 64) {
        const float inv = 1.f / (float)HW;
        float2 s = ((const float2*)rawst)[b*64 + tid];
        float m = s.x * inv;
        float v = s.y * inv - m*m;
        *(float2*)(smem + OF_NRM + tid*8) = make_float2(m, rsqrtf(v + EPS));
    }
    // kick off B stage 0 copy (buffer 0) while nrm settles
    const uint4* wp4 = (const uint4*)wp;   // [18][512] uint4
    cpasync16(sb + OF_B + (uint32_t)tid*16,         wp4 + tid);
    cpasync16(sb + OF_B + (uint32_t)(tid + 256)*16, wp4 + tid + 256);
    CPASYNC_COMMIT();
    __syncthreads();   // nrm visible before window fill

    // ---- window fill: 340 rows (10h x 34w) x 64 ci ----
    for (int g = tid; g < 2720; g += 256) {
        const int chunk = g / 340;
        const int r = g - chunk*340;
        const int rr = r / 34, cc = r - rr*34;
        int gh = tileH*8 - 1 + rr; gh = gh < 0 ? 0 : (gh > H-1 ? H-1 : gh);
        int gw = tileW*32 - 1 + cc; gw = gw < 0 ? 0 : (gw > W-1 ? W-1 : gw);
        const float* src = in + ((size_t)(b*64 + chunk*8))*HW + gh*W + gw;
        unsigned short hb[8], lb[8];
        #pragma unroll
        for (int q = 0; q < 8; q++) {
            const int ci = chunk*8 + q;
            float2 mr = *(const float2*)(smem + OF_NRM + ci*8);
            float x = __ldg(src + (size_t)q*HW);
            x = (x - mr.x) * mr.y;
            x = x >= 0.f ? x : SLOPE * x;
            __half h = __float2half_rn(x);
            float xhf = __half2float(h);
            __half l = __float2half_rn((x - xhf) + CSPL*xhf);   // a2 = xl + c*xh
            hb[q] = *(unsigned short*)&h;
            lb[q] = *(unsigned short*)&l;
        }
        const uint32_t off = (uint32_t)r*128 + (uint32_t)((chunk ^ (r & 7)) << 4);
        *(uint4*)(smem + OF_WHI + off) = *(uint4*)hb;
        *(uint4*)(smem + OF_WLO + off) = *(uint4*)lb;
    }
    CPASYNC_WAIT0();
    __syncthreads();   // window + B stage 0 visible

    // warp geometry: 4 M-strips (64 px = two h-rows) x 2 N-halves (32 co)
    const int mwid = wid >> 1;           // 0..3
    const int nwid = wid & 1;            // 0..1
    const int gA  = lane >> 3;
    const int rl  = (lane & 7) + (gA & 1)*8;
    const int aK  = gA >> 1;
    const int bRow = (lane & 7) + ((lane >> 4) & 1)*8;
    const int bK   = (lane >> 3) & 1;
    const int bsw  = lane & 7;

    float d[4][4][4];   // [mf][n8][frag]
    #pragma unroll
    for (int mf = 0; mf < 4; mf++)
        #pragma unroll
        for (int n = 0; n < 4; n++)
            #pragma unroll
            for (int j = 0; j < 4; j++) d[mf][n][j] = 0.f;

    #pragma unroll 1
    for (int tt = 0; tt < 18; tt++) {
        // kick off next stage's B copy into the other buffer (its readers done at prev barrier)
        if (tt < 17) {
            const uint4* np = wp4 + (size_t)(tt + 1)*512;
            const uint32_t dst = sb + OF_B + (uint32_t)((tt + 1) & 1)*8192;
            cpasync16(dst + (uint32_t)tid*16,         np + tid);
            cpasync16(dst + (uint32_t)(tid + 256)*16, np + tid + 256);
            CPASYNC_COMMIT();
        }

        // between passes: d *= (1 - c)  (exactly once, after all pass-1 MMAs)
        if (tt == 9) {
            #pragma unroll
            for (int mf = 0; mf < 4; mf++)
                #pragma unroll
                for (int n = 0; n < 4; n++)
                    #pragma unroll
                    for (int j = 0; j < 4; j++) d[mf][n][j] *= (1.0f - CSPL);
        }

        const int t  = tt < 9 ? tt : tt - 9;
        const int kh = t / 3, kw = t - kh*3;
        const uint32_t aBase = sb + (tt < 9 ? OF_WHI : OF_WLO);
        int wr[4];
        #pragma unroll
        for (int mf = 0; mf < 4; mf++) {
            const int hh = mwid*2 + (mf >> 1);
            wr[mf] = (hh + kh)*34 + (mf & 1)*16 + kw + rl;
        }
        const uint32_t bB = sb + OF_B + (uint32_t)(tt & 1)*8192;

        #pragma unroll
        for (int ks = 0; ks < 4; ks++) {
            uint32_t a[4][4];
            #pragma unroll
            for (int mf = 0; mf < 4; mf++)
                ldsm4(a[mf], aBase + (uint32_t)wr[mf]*128
                              + (uint32_t)(((2*ks + aK) ^ (wr[mf] & 7)) << 4));
            uint32_t bf[2][4];
            const uint32_t cb = (uint32_t)(((2*ks + bK) ^ bsw) << 4);
            #pragma unroll
            for (int nn = 0; nn < 2; nn++)
                ldsm4(bf[nn], bB + (uint32_t)((nwid*2 + nn)*16 + bRow)*128 + cb);
            #pragma unroll
            for (int mf = 0; mf < 4; mf++)
                #pragma unroll
                for (int n = 0; n < 4; n++)
                    mma16816h(d[mf][n], a[mf], &bf[n >> 1][(n & 1)*2]);
        }

        if (tt < 17) {
            CPASYNC_WAIT0();
            __syncthreads();   // next-stage B visible; prev buffer free for overwrite
        }
    }

    // ---- epilogue: d -> smem (stride 264) -> coalesced store + fused stats ----
    __syncthreads();   // window reads done; safe to overwrite
    float* epi = (float*)smem;
    #pragma unroll
    for (int mf = 0; mf < 4; mf++)
        #pragma unroll
        for (int n = 0; n < 4; n++)
            #pragma unroll
            for (int j = 0; j < 4; j++) {
                const int r16 = (lane >> 2) + ((j >> 1) << 3);
                const int px = (mwid*2 + (mf >> 1))*32 + (mf & 1)*16 + r16;
                const int co = nwid*32 + n*8 + (lane & 3)*2 + (j & 1);
                epi[co*EPI_STRIDE + px] = d[mf][n][j];
            }
    __syncthreads();

    {
        const int h0 = tileH*8, w0 = tileW*32;
        #pragma unroll 1
        for (int k = 0; k < 8; k++) {
            const int co = wid*8 + k;
            const float bv = __ldg(bias + co);
            float* op = out + ((size_t)(b*64 + co))*HW + (size_t)h0*W + w0;
            float s = 0.f, q = 0.f;
            #pragma unroll
            for (int i = 0; i < 8; i++) {
                float v = epi[co*EPI_STRIDE + i*32 + lane] + bv;
                op[(size_t)i*W + lane] = v;
                s += v; q += v*v;
            }
            #pragma unroll
            for (int off = 16; off; off >>= 1) {
                s += __shfl_down_sync(0xffffffffu, s, off);
                q += __shfl_down_sync(0xffffffffu, q, off);
            }
            if (lane == 0) {
                atomicAdd(&statacc[(b*64 + co)*2    ], s);
                atomicAdd(&statacc[(b*64 + co)*2 + 1], q);
            }
        }
    }
}

// ---------------- layer-0 scalar conv (cin=1, proven; raw stats out) ----------------
__global__ __launch_bounds__(256, 2)
void conv_kernel(const float* __restrict__ in,
                 const float* __restrict__ wgt,
                 const float* __restrict__ bias,
                 float* __restrict__ out,
                 float* __restrict__ statacc,
                 int cin)
{
    __shared__ float s_w[64*9*16];
    __shared__ float s_in[2][18*36];

    const int tid   = threadIdx.x;
    const int tileW = blockIdx.x & 7;
    const int tileH = blockIdx.x >> 3;
    const int co_base = blockIdx.y * 16;
    const int b = blockIdx.z;

    const int nw = cin * 9 * 16;
    for (int g = tid; g < nw; g += 256) {
        int co_l = g & 15;
        int ct   = g >> 4;
        int ci   = ct / 9;
        int t    = ct - ci*9;
        s_w[g] = wgt[((co_base + co_l)*cin + ci)*9 + t];
    }

    const int sp = tid & 63, cg = tid >> 6;
    const int ph = sp >> 3, pw = sp & 7;
    const int h0 = tileH*16 + ph*2;
    const int w0 = tileW*32 + pw*4;
    const int hbase = tileH*16 - 1, wbase = tileW*32 - 1;

    int srcO[3], dstO[3]; bool act[3];
    #pragma unroll
    for (int k = 0; k < 3; k++) {
        int g = tid + k*256;
        act[k] = (g < 612);
        int gg = act[k] ? g : 0;
        int r = gg / 34, c = gg - r * 34;
        int gh = hbase + r; gh = gh < 0 ? 0 : (gh > H-1 ? H-1 : gh);
        int gw = wbase + c; gw = gw < 0 ? 0 : (gw > W-1 ? W-1 : gw);
        srcO[k] = gh*W + gw;
        dstO[k] = r*36 + c;
    }

    const float* inb = in + (size_t)b * cin * HW;

    #pragma unroll
    for (int k = 0; k < 3; k++) if (act[k])
        s_in[0][dstO[k]] = inb[srcO[k]];
    __syncthreads();

    u64 acc[2][2][4];
    #pragma unroll
    for (int p = 0; p < 2; p++)
        #pragma unroll
        for (int i = 0; i < 2; i++)
            #pragma unroll
            for (int j = 0; j < 4; j++) acc[p][i][j] = 0ull;

    for (int ci = 0; ci < cin; ci++) {
        const int buf = ci & 1;
        const int cn = (ci + 1 < cin) ? ci + 1 : cin - 1;

        float pre[3];
        {
            const float* pn = inb + (size_t)cn * HW;
            #pragma unroll
            for (int k = 0; k < 3; k++) pre[k] = act[k] ? pn[srcO[k]] : 0.f;
        }

        u64 dup[4][6];
        #pragma unroll
        for (int r = 0; r < 4; r++) {
            const float* row = &s_in[buf][(ph*2 + r)*36 + pw*4];
            float4 v4 = *reinterpret_cast<const float4*>(row);
            float2 v2 = *reinterpret_cast<const float2*>(row + 4);
            PACK2(dup[r][0], v4.x, v4.x);
            PACK2(dup[r][1], v4.y, v4.y);
            PACK2(dup[r][2], v4.z, v4.z);
            PACK2(dup[r][3], v4.w, v4.w);
            PACK2(dup[r][4], v2.x, v2.x);
            PACK2(dup[r][5], v2.y, v2.y);
        }

        const float* wrow = &s_w[ci*9*16 + cg*4];
        #pragma unroll
        for (int p = 0; p < 2; p++) {
            u64 wv[9];
            #pragma unroll
            for (int t = 0; t < 9; t++)
                wv[t] = *reinterpret_cast<const u64*>(&wrow[t*16 + p*2]);
            #pragma unroll
            for (int kh = 0; kh < 3; kh++)
                #pragma unroll
                for (int kw = 0; kw < 3; kw++)
                    #pragma unroll
                    for (int i = 0; i < 2; i++)
                        #pragma unroll
                        for (int j = 0; j < 4; j++)
                            FMA2(acc[p][i][j], dup[i+kh][j+kw], wv[kh*3+kw], acc[p][i][j]);
        }

        #pragma unroll
        for (int k = 0; k < 3; k++) if (act[k])
            s_in[buf ^ 1][dstO[k]] = pre[k];
        __syncthreads();
    }

    #pragma unroll
    for (int p = 0; p < 2; p++) {
        const int co0 = co_base + cg*4 + 2*p;
        const float bv0 = bias[co0], bv1 = bias[co0 + 1];
        float* ob0 = out + (size_t)(b*CH + co0    ) * HW;
        float* ob1 = out + (size_t)(b*CH + co0 + 1) * HW;
        float s0 = 0.f, q0 = 0.f, s1 = 0.f, q1 = 0.f;
        #pragma unroll
        for (int i = 0; i < 2; i++) {
            float lo[4], hi[4];
            #pragma unroll
            for (int j = 0; j < 4; j++) {
                float l, h2;
                UNPK2(l, h2, acc[p][i][j]);
                lo[j] = l + bv0; hi[j] = h2 + bv1;
                s0 += lo[j]; q0 += lo[j]*lo[j];
                s1 += hi[j]; q1 += hi[j]*hi[j];
            }
            *reinterpret_cast<float4*>(&ob0[(h0+i)*W + w0]) = make_float4(lo[0],lo[1],lo[2],lo[3]);
            *reinterpret_cast<float4*>(&ob1[(h0+i)*W + w0]) = make_float4(hi[0],hi[1],hi[2],hi[3]);
        }
        #pragma unroll
        for (int off = 16; off; off >>= 1) {
            s0 += __shfl_down_sync(0xffffffffu, s0, off);
            q0 += __shfl_down_sync(0xffffffffu, q0, off);
            s1 += __shfl_down_sync(0xffffffffu, s1, off);
            q1 += __shfl_down_sync(0xffffffffu, q1, off);
        }
        if ((tid & 31) == 0) {
            atomicAdd(&statacc[(b*CH + co0)*2    ], s0);
            atomicAdd(&statacc[(b*CH + co0)*2 + 1], q0);
            atomicAdd(&statacc[(b*CH + co0+1)*2    ], s1);
            atomicAdd(&statacc[(b*CH + co0+1)*2 + 1], q1);
        }
    }
}

// ---------------- projection conv (64->1) + residual: 16x32 tile, dbl-buffered ----------------
__global__ __launch_bounds__(256)
void proj_kernel(const float* __restrict__ in, const float* __restrict__ rawst,
                 const float* __restrict__ wgt, const float* __restrict__ bias,
                 const float* __restrict__ xIn, float* __restrict__ out)
{
    __shared__ float s_w[64*9];
    __shared__ float2 s_nrm[64];
    __shared__ float s_in[2][18*36];
    const int tid = threadIdx.x;
    const int tileW = blockIdx.x & 7;
    const int tileH = blockIdx.x >> 3;   // 0..15
    const int b = blockIdx.z;

    for (int g = tid; g < 576; g += 256) s_w[g] = wgt[g];
    if (tid < 64) {
        const float inv = 1.f / (float)HW;
        float2 s = ((const float2*)rawst)[b*64 + tid];
        float m = s.x * inv;
        float v = s.y * inv - m*m;
        s_nrm[tid] = make_float2(m, rsqrtf(v + EPS));
    }
    __syncthreads();

    const int pw = tid & 31, hp = tid >> 5;  // w 0..31, hpair 0..7
    const int h0 = tileH*16 + hp*2;
    const int w0 = tileW*32 + pw;
    const int hbase = tileH*16 - 1, wbase = tileW*32 - 1;

    int srcO[3], dstO[3]; bool act[3];
    #pragma unroll
    for (int k = 0; k < 3; k++) {
        int g = tid + k*256;
        act[k] = (g < 612);
        int gg = act[k] ? g : 0;
        int r = gg / 34, c = gg - r*34;
        int gh = hbase + r; gh = gh < 0 ? 0 : (gh > H-1 ? H-1 : gh);
        int gw = wbase + c; gw = gw < 0 ? 0 : (gw > W-1 ? W-1 : gw);
        srcO[k] = gh*W + gw;
        dstO[k] = r*36 + c;
    }

    const float* inb = in + (size_t)b*64*HW;

    {
        float2 mr = s_nrm[0];
        #pragma unroll
        for (int k = 0; k < 3; k++) if (act[k]) {
            float v = inb[srcO[k]];
            v = (v - mr.x) * mr.y;
            v = v >= 0.f ? v : SLOPE * v;
            s_in[0][dstO[k]] = v;
        }
    }
    __syncthreads();

    float acc0 = 0.f, acc1 = 0.f;
    for (int ci = 0; ci < 64; ci++) {
        const int buf = ci & 1;
        const int cn = (ci + 1 < 64) ? ci + 1 : 63;
        float pre[3];
        float2 nmr = s_nrm[cn];
        {
            const float* pn = inb + (size_t)cn*HW;
            #pragma unroll
            for (int k = 0; k < 3; k++) pre[k] = act[k] ? pn[srcO[k]] : 0.f;
        }

        float rr[4][3];
        #pragma unroll
        for (int r = 0; r < 4; r++)
            #pragma unroll
            for (int c = 0; c < 3; c++)
                rr[r][c] = s_in[buf][(hp*2 + r)*36 + pw + c];

        const float* wv = &s_w[ci*9];
        #pragma unroll
        for (int kh = 0; kh < 3; kh++)
            #pragma unroll
            for (int kw = 0; kw < 3; kw++) {
                float wvv = wv[kh*3 + kw];
                acc0 = fmaf(rr[kh    ][kw], wvv, acc0);
                acc1 = fmaf(rr[kh + 1][kw], wvv, acc1);
            }

        #pragma unroll
        for (int k = 0; k < 3; k++) if (act[k]) {
            float v = pre[k];
            v = (v - nmr.x) * nmr.y;
            v = v >= 0.f ? v : SLOPE * v;
            s_in[buf ^ 1][dstO[k]] = v;
        }
        __syncthreads();
    }

    int idx = b*HW + h0*W + w0;
    out[idx]     = acc0 + bias[0] + xIn[idx];
    out[idx + W] = acc1 + bias[0] + xIn[idx + W];
}

// ---------------- shift-search loss: streaming partials ----------------
__global__ __launch_bounds__(256)
void loss_part_kernel(const float* __restrict__ hr, const float* __restrict__ tgt)
{
    const int sy = blockIdx.x, rc = blockIdx.y, b = blockIdx.z;
    const int tid = threadIdx.x;
    const int lane = tid & 31;
    __shared__ float s_hr[2][256];
    __shared__ float s_t[2][244];

    const float* hp = hr  + (size_t)b*HW;
    const float* tp = tgt + (size_t)b*HW;
    const int r0 = rc*61;

    float X[13], S1[13], S2[13];
    #pragma unroll
    for (int s = 0; s < 13; s++) { X[s] = 0.f; S1[s] = 0.f; S2[s] = 0.f; }
    float t1 = 0.f, t2 = 0.f;

    s_hr[0][tid] = hp[(sy + r0)*W + tid];
    if (tid < CROP) s_t[0][tid] = tp[(6 + r0)*W + 6 + tid];
    __syncthreads();

    for (int r = 0; r < 61; r++) {
        const int buf = r & 1;
        float hv = 0.f, tv = 0.f;
        if (r < 60) {
            hv = hp[(sy + r0 + r + 1)*W + tid];
            if (tid < CROP) tv = tp[(6 + r0 + r + 1)*W + 6 + tid];
        }
        if (tid < CROP) {
            const float tc = s_t[buf][tid];
            t1 += tc; t2 = fmaf(tc, tc, t2);
            #pragma unroll
            for (int s = 0; s < 13; s++) {
                const float v = s_hr[buf][s + tid];
                X[s]  = fmaf(v, tc, X[s]);
                S1[s] += v;
                S2[s] = fmaf(v, v, S2[s]);
            }
        }
        if (r < 60) {
            s_hr[buf ^ 1][tid] = hv;
            if (tid < CROP) s_t[buf ^ 1][tid] = tv;
        }
        __syncthreads();
    }

    float* part = g_loss_part + ((size_t)(b*13 + sy))*13*3;
    #pragma unroll
    for (int s = 0; s < 13; s++) {
        float x = X[s], a = S1[s], q = S2[s];
        #pragma unroll
        for (int off = 16; off; off >>= 1) {
            x += __shfl_down_sync(0xffffffffu, x, off);
            a += __shfl_down_sync(0xffffffffu, a, off);
            q += __shfl_down_sync(0xffffffffu, q, off);
        }
        if (lane == 0) {
            atomicAdd(&part[s*3    ], x);
            atomicAdd(&part[s*3 + 1], a);
            atomicAdd(&part[s*3 + 2], q);
        }
    }
    if (sy == 0) {
        #pragma unroll
        for (int off = 16; off; off >>= 1) {
            t1 += __shfl_down_sync(0xffffffffu, t1, off);
            t2 += __shfl_down_sync(0xffffffffu, t2, off);
        }
        if (lane == 0) {
            atomicAdd(&g_loss_t[b*2    ], t1);
            atomicAdd(&g_loss_t[b*2 + 1], t2);
        }
    }
}

__global__ __launch_bounds__(256)
void loss_final_kernel(float* __restrict__ outp) {
    __shared__ float mn[256];
    const float invN = 1.f / ((float)CROP * (float)CROP);
    float total = 0.f;
    for (int b = 0; b < BSZ; b++) {
        float v = 1e30f;
        if (threadIdx.x < 169) {
            const float* part = g_loss_part + ((size_t)b*169 + threadIdx.x)*3;
            const float Xv = part[0], S1 = part[1], S2 = part[2];
            const float T1 = g_loss_t[b*2], T2 = g_loss_t[b*2 + 1];
            const float e2 = (S2 - 2.f*Xv + T2) * invN;
            const float e1 = (S1 - T1) * invN;
            v = e2 - e1*e1;
        }
        mn[threadIdx.x] = v;
        __syncthreads();
        for (int off = 128; off; off >>= 1) {
            if (threadIdx.x < off) mn[threadIdx.x] = fminf(mn[threadIdx.x], mn[threadIdx.x + off]);
            __syncthreads();
        }
        if (threadIdx.x == 0) total += mn[0];
        __syncthreads();
    }
    if (threadIdx.x == 0) outp[0] = total * (1.f / BSZ);
}

// ---------------- launch ----------------
extern "C" void kernel_launch(void* const* d_in, const int* in_sizes, int n_in,
                              void* d_out, int out_size)
{
    const float* xIn    = (const float*)d_in[0];
    const float* target = (const float*)d_in[1];
    const float* w0     = (const float*)d_in[2];
    const float* b0     = (const float*)d_in[3];
    const float* ws     = (const float*)d_in[4];
    const float* bs     = (const float*)d_in[5];
    const float* wp     = (const float*)d_in[6];
    const float* bp     = (const float*)d_in[7];
    float* out = (float*)d_out;

    static int attr_done = 0;
    if (!attr_done) {
        cudaFuncSetAttribute(mma_conv_kernel, cudaFuncAttributeMaxDynamicSharedMemorySize, SMEM_MMA);
        attr_done = 1;
    }

    float *actA, *actB, *stats;
    __half* wprep;
    cudaGetSymbolAddress((void**)&actA,  g_actA);
    cudaGetSymbolAddress((void**)&actB,  g_actB);
    cudaGetSymbolAddress((void**)&stats, g_stats);
    cudaGetSymbolAddress((void**)&wprep, g_wprep);

    // launch 1: weight prep + accumulator zeroing
    wprep_kernel<<<dim3(9, 7), 256>>>(ws);

    // launch 2: layer 0 (1 -> 64) scalar path, raw stats -> slot 0
    conv_kernel<<<dim3(128, 4, BSZ), 256>>>(xIn, w0, b0, actA, stats, 1);

    const float* cur = actA;
    float* nxt = actB;
    for (int i = 0; i < 7; i++) {
        mma_conv_kernel<<<dim3(8, 32, BSZ), 256, SMEM_MMA>>>(
            cur, wprep + (size_t)i*18*4096, bs + i*64,
            stats + (size_t)i*BSZ*CH*2, nxt, stats + (size_t)(i+1)*BSZ*CH*2);
        float* tmp = (float*)cur; cur = nxt; nxt = tmp;
    }

    proj_kernel<<<dim3(128, 1, BSZ), 256>>>(cur, stats + (size_t)7*BSZ*CH*2,
                                            wp, bp, xIn, out);
    loss_part_kernel<<<dim3(13, 4, BSZ), 256>>>(out, target);
    loss_final_kernel<<<1, 256>>>(out + (out_size - 1));
}

// round 16
// speedup vs baseline: 1.0398x; 1.0398x over previous
#include <cuda_runtime.h>
#include <cuda_fp16.h>
#include <cstdint>

#define BSZ 8
#define CH  64
#define H   256
#define W   256
#define HW  (H*W)
#define EPS 1e-5f
#define SLOPE 0.01f
#define CROP 244
#define CSPL 0.03125f   // c = 2^-5 split-compensation constant

typedef unsigned long long u64;

#define FMA2(d,a,b,c) asm("fma.rn.f32x2 %0, %1, %2, %3;" : "=l"(d) : "l"(a), "l"(b), "l"(c))
#define PACK2(d,lo,hi) asm("mov.b64 %0, {%1, %2};" : "=l"(d) : "f"(lo), "f"(hi))
#define UNPK2(lo,hi,d) asm("mov.b64 {%0, %1}, %2;" : "=f"(lo), "=f"(hi) : "l"(d))

__device__ __forceinline__ uint32_t smem_u32(const void* p) {
    uint32_t a;
    asm("{ .reg .u64 t; cvta.to.shared.u64 t, %1; cvt.u32.u64 %0, t; }" : "=r"(a) : "l"(p));
    return a;
}
__device__ __forceinline__ void ldsm4(uint32_t* r, uint32_t addr) {
    asm volatile("ldmatrix.sync.aligned.m8n8.x4.shared.b16 {%0,%1,%2,%3}, [%4];"
                 : "=r"(r[0]), "=r"(r[1]), "=r"(r[2]), "=r"(r[3]) : "r"(addr));
}
__device__ __forceinline__ void mma16816h(float* d, const uint32_t* a, const uint32_t* b) {
    asm volatile("mma.sync.aligned.m16n8k16.row.col.f32.f16.f16.f32 "
                 "{%0,%1,%2,%3}, {%4,%5,%6,%7}, {%8,%9}, {%0,%1,%2,%3};"
                 : "+f"(d[0]), "+f"(d[1]), "+f"(d[2]), "+f"(d[3])
                 : "r"(a[0]), "r"(a[1]), "r"(a[2]), "r"(a[3]), "r"(b[0]), "r"(b[1]));
}

// ---------------- scratch ----------------
__device__ float g_actA[BSZ*CH*HW];
__device__ float g_actB[BSZ*CH*HW];
__device__ float g_stats[8*BSZ*CH*2];
__device__ float g_loss_part[BSZ*13*13*3];   // (X, S1hr, S2hr) per (b, sy, sx)
__device__ float g_loss_t[BSZ*2];            // (S1t, S2t) per b
// [layer][img(bh=0,b2=1)][tap][4096] fp16 ldmatrix-swizzled co x ci images (R12-proven layout)
__device__ __half g_wprep[7*2*9*4096];

// ---------------- weight prep: wh image + compensated w2 image (+ zero accums) ----------------
// image layout: byte_off = co*128 + (((ci>>3) ^ (co&7))<<4) + (ci&7)*2
__global__ void wprep_kernel(const float* __restrict__ ws) {
    const int t = blockIdx.x;    // tap 0..8
    const int l = blockIdx.y;    // layer 0..6
    if (t == 0 && l == 0) {      // fold accumulator zeroing into this launch
        for (int i = threadIdx.x; i < 8*BSZ*CH*2; i += blockDim.x) g_stats[i] = 0.f;
        for (int i = threadIdx.x; i < BSZ*13*13*3; i += blockDim.x) g_loss_part[i] = 0.f;
        if (threadIdx.x < BSZ*2) g_loss_t[threadIdx.x] = 0.f;
    }
    char* dst0 = (char*)(g_wprep + ((size_t)l*18 +     t)*4096);   // bh
    char* dst1 = (char*)(g_wprep + ((size_t)l*18 + 9 + t)*4096);   // b2
    for (int g = threadIdx.x; g < 4096; g += blockDim.x) {
        int co = g >> 6, ci = g & 63;
        float w = ws[(((size_t)l*64 + co)*64 + ci)*9 + t];
        __half wh = __float2half_rn(w);
        float whf = __half2float(wh);
        __half w2 = __float2half_rn(whf + 32.0f*(w - whf));   // wh + wl/c
        uint32_t off = (uint32_t)co*128 + ((((uint32_t)ci >> 3) ^ (co & 7)) << 4) + (ci & 7)*2;
        *(__half*)(dst0 + off) = wh;
        *(__half*)(dst1 + off) = w2;
    }
}

// ---------------- HMMA conv layer: M256 tile, sequential compensated 2-pass ----------------
// smem: window xh [340*128B], window a2 [340*128B], B dbl [2*8KB], nrm [512B]
#define OF_WHI 0
#define OF_WLO 43520
#define OF_B   87040
#define OF_NRM 103424
#define SMEM_MMA 103936
#define EPI_STRIDE 264

__global__ void __launch_bounds__(256, 2)
mma_conv_kernel(const float* __restrict__ in,
                const __half* __restrict__ wp,          // this layer: [2][9][4096]
                const float* __restrict__ bias,
                const float* __restrict__ rawst,        // [BSZ*64*2] raw (sum, sumsq) of input
                float* __restrict__ out,
                float* __restrict__ statacc)            // [BSZ*64*2] raw accum for output
{
    extern __shared__ char smem[];
    const uint32_t sb = smem_u32(smem);
    const int tid = threadIdx.x;
    const int wid = tid >> 5, lane = tid & 31;
    const int tileW = blockIdx.x;   // 0..7   (32 w)
    const int tileH = blockIdx.y;   // 0..31  (8 h)
    const int b = blockIdx.z;

    // folded finalize: raw (sum, sumsq) -> (mean, rstd)
    if (tid < 64) {
        const float inv = 1.f / (float)HW;
        float2 s = ((const float2*)rawst)[b*64 + tid];
        float m = s.x * inv;
        float v = s.y * inv - m*m;
        *(float2*)(smem + OF_NRM + tid*8) = make_float2(m, rsqrtf(v + EPS));
    }
    __syncthreads();   // nrm visible before window fill

    // ---- window fill: 340 rows (10h x 34w) x 64 ci ----
    for (int g = tid; g < 2720; g += 256) {
        const int chunk = g / 340;
        const int r = g - chunk*340;
        const int rr = r / 34, cc = r - rr*34;
        int gh = tileH*8 - 1 + rr; gh = gh < 0 ? 0 : (gh > H-1 ? H-1 : gh);
        int gw = tileW*32 - 1 + cc; gw = gw < 0 ? 0 : (gw > W-1 ? W-1 : gw);
        const float* src = in + ((size_t)(b*64 + chunk*8))*HW + gh*W + gw;
        unsigned short hb[8], lb[8];
        #pragma unroll
        for (int q = 0; q < 8; q++) {
            const int ci = chunk*8 + q;
            float2 mr = *(const float2*)(smem + OF_NRM + ci*8);
            float x = __ldg(src + (size_t)q*HW);
            x = (x - mr.x) * mr.y;
            x = x >= 0.f ? x : SLOPE * x;
            __half h = __float2half_rn(x);
            float xhf = __half2float(h);
            __half l = __float2half_rn((x - xhf) + CSPL*xhf);   // a2 = xl + c*xh
            hb[q] = *(unsigned short*)&h;
            lb[q] = *(unsigned short*)&l;
        }
        const uint32_t off = (uint32_t)r*128 + (uint32_t)((chunk ^ (r & 7)) << 4);
        *(uint4*)(smem + OF_WHI + off) = *(uint4*)hb;
        *(uint4*)(smem + OF_WLO + off) = *(uint4*)lb;
    }

    // ---- stage B for tt=0 (bh, tap 0) into buffer 0 ----
    const uint4* wp4 = (const uint4*)wp;   // [18][512] uint4
    *(uint4*)(smem + OF_B + (uint32_t)tid*16)         = __ldg(wp4 + tid);
    *(uint4*)(smem + OF_B + (uint32_t)(tid + 256)*16) = __ldg(wp4 + tid + 256);
    __syncthreads();

    // warp geometry: 4 M-strips (64 px = two h-rows) x 2 N-halves (32 co)
    const int mwid = wid >> 1;           // 0..3
    const int nwid = wid & 1;            // 0..1
    const int gA  = lane >> 3;
    const int rl  = (lane & 7) + (gA & 1)*8;
    const int aK  = gA >> 1;
    const int bRow = (lane & 7) + ((lane >> 4) & 1)*8;
    const int bK   = (lane >> 3) & 1;
    const int bsw  = lane & 7;

    float d[4][4][4];   // [mf][n8][frag]
    #pragma unroll
    for (int mf = 0; mf < 4; mf++)
        #pragma unroll
        for (int n = 0; n < 4; n++)
            #pragma unroll
            for (int j = 0; j < 4; j++) d[mf][n][j] = 0.f;

    #pragma unroll 1
    for (int tt = 0; tt < 18; tt++) {
        // prefetch next stage's B image tap into registers
        uint4 pre0, pre1;
        if (tt < 17) {
            const uint4* np = wp4 + (size_t)(tt + 1)*512;
            pre0 = __ldg(np + tid);
            pre1 = __ldg(np + tid + 256);
        }

        // between passes: d *= (1 - c)  (exactly once, after all pass-1 MMAs)
        if (tt == 9) {
            #pragma unroll
            for (int mf = 0; mf < 4; mf++)
                #pragma unroll
                for (int n = 0; n < 4; n++)
                    #pragma unroll
                    for (int j = 0; j < 4; j++) d[mf][n][j] *= (1.0f - CSPL);
        }

        const int t  = tt < 9 ? tt : tt - 9;
        const int kh = t / 3, kw = t - kh*3;
        const uint32_t aBase = sb + (tt < 9 ? OF_WHI : OF_WLO);
        int wr[4];
        #pragma unroll
        for (int mf = 0; mf < 4; mf++) {
            const int hh = mwid*2 + (mf >> 1);
            wr[mf] = (hh + kh)*34 + (mf & 1)*16 + kw + rl;
        }
        const uint32_t bB = sb + OF_B + (uint32_t)(tt & 1)*8192;

        #pragma unroll
        for (int ks = 0; ks < 4; ks++) {
            uint32_t a[4][4];
            #pragma unroll
            for (int mf = 0; mf < 4; mf++)
                ldsm4(a[mf], aBase + (uint32_t)wr[mf]*128
                              + (uint32_t)(((2*ks + aK) ^ (wr[mf] & 7)) << 4));
            uint32_t bf[2][4];
            const uint32_t cb = (uint32_t)(((2*ks + bK) ^ bsw) << 4);
            #pragma unroll
            for (int nn = 0; nn < 2; nn++)
                ldsm4(bf[nn], bB + (uint32_t)((nwid*2 + nn)*16 + bRow)*128 + cb);
            #pragma unroll
            for (int mf = 0; mf < 4; mf++)
                #pragma unroll
                for (int n = 0; n < 4; n++)
                    mma16816h(d[mf][n], a[mf], &bf[n >> 1][(n & 1)*2]);
        }

        if (tt < 17) {
            char* dst = smem + OF_B + (uint32_t)((tt + 1) & 1)*8192;
            *(uint4*)(dst + (uint32_t)tid*16)         = pre0;
            *(uint4*)(dst + (uint32_t)(tid + 256)*16) = pre1;
            __syncthreads();
        }
    }

    // ---- epilogue: d -> smem (stride 264) -> coalesced store + fused stats ----
    __syncthreads();   // window reads done; safe to overwrite
    float* epi = (float*)smem;
    #pragma unroll
    for (int mf = 0; mf < 4; mf++)
        #pragma unroll
        for (int n = 0; n < 4; n++)
            #pragma unroll
            for (int j = 0; j < 4; j++) {
                const int r16 = (lane >> 2) + ((j >> 1) << 3);
                const int px = (mwid*2 + (mf >> 1))*32 + (mf & 1)*16 + r16;
                const int co = nwid*32 + n*8 + (lane & 3)*2 + (j & 1);
                epi[co*EPI_STRIDE + px] = d[mf][n][j];
            }
    __syncthreads();

    {
        const int h0 = tileH*8, w0 = tileW*32;
        #pragma unroll 1
        for (int k = 0; k < 8; k++) {
            const int co = wid*8 + k;
            const float bv = __ldg(bias + co);
            float* op = out + ((size_t)(b*64 + co))*HW + (size_t)h0*W + w0;
            float s = 0.f, q = 0.f;
            #pragma unroll
            for (int i = 0; i < 8; i++) {
                float v = epi[co*EPI_STRIDE + i*32 + lane] + bv;
                op[(size_t)i*W + lane] = v;
                s += v; q += v*v;
            }
            #pragma unroll
            for (int off = 16; off; off >>= 1) {
                s += __shfl_down_sync(0xffffffffu, s, off);
                q += __shfl_down_sync(0xffffffffu, q, off);
            }
            if (lane == 0) {
                atomicAdd(&statacc[(b*64 + co)*2    ], s);
                atomicAdd(&statacc[(b*64 + co)*2 + 1], q);
            }
        }
    }
}

// ---------------- layer-0 scalar conv (cin=1, proven; raw stats out) ----------------
__global__ __launch_bounds__(256, 2)
void conv_kernel(const float* __restrict__ in,
                 const float* __restrict__ wgt,
                 const float* __restrict__ bias,
                 float* __restrict__ out,
                 float* __restrict__ statacc,
                 int cin)
{
    __shared__ float s_w[64*9*16];
    __shared__ float s_in[2][18*36];

    const int tid   = threadIdx.x;
    const int tileW = blockIdx.x & 7;
    const int tileH = blockIdx.x >> 3;
    const int co_base = blockIdx.y * 16;
    const int b = blockIdx.z;

    const int nw = cin * 9 * 16;
    for (int g = tid; g < nw; g += 256) {
        int co_l = g & 15;
        int ct   = g >> 4;
        int ci   = ct / 9;
        int t    = ct - ci*9;
        s_w[g] = wgt[((co_base + co_l)*cin + ci)*9 + t];
    }

    const int sp = tid & 63, cg = tid >> 6;
    const int ph = sp >> 3, pw = sp & 7;
    const int h0 = tileH*16 + ph*2;
    const int w0 = tileW*32 + pw*4;
    const int hbase = tileH*16 - 1, wbase = tileW*32 - 1;

    int srcO[3], dstO[3]; bool act[3];
    #pragma unroll
    for (int k = 0; k < 3; k++) {
        int g = tid + k*256;
        act[k] = (g < 612);
        int gg = act[k] ? g : 0;
        int r = gg / 34, c = gg - r * 34;
        int gh = hbase + r; gh = gh < 0 ? 0 : (gh > H-1 ? H-1 : gh);
        int gw = wbase + c; gw = gw < 0 ? 0 : (gw > W-1 ? W-1 : gw);
        srcO[k] = gh*W + gw;
        dstO[k] = r*36 + c;
    }

    const float* inb = in + (size_t)b * cin * HW;

    #pragma unroll
    for (int k = 0; k < 3; k++) if (act[k])
        s_in[0][dstO[k]] = inb[srcO[k]];
    __syncthreads();

    u64 acc[2][2][4];
    #pragma unroll
    for (int p = 0; p < 2; p++)
        #pragma unroll
        for (int i = 0; i < 2; i++)
            #pragma unroll
            for (int j = 0; j < 4; j++) acc[p][i][j] = 0ull;

    for (int ci = 0; ci < cin; ci++) {
        const int buf = ci & 1;
        const int cn = (ci + 1 < cin) ? ci + 1 : cin - 1;

        float pre[3];
        {
            const float* pn = inb + (size_t)cn * HW;
            #pragma unroll
            for (int k = 0; k < 3; k++) pre[k] = act[k] ? pn[srcO[k]] : 0.f;
        }

        u64 dup[4][6];
        #pragma unroll
        for (int r = 0; r < 4; r++) {
            const float* row = &s_in[buf][(ph*2 + r)*36 + pw*4];
            float4 v4 = *reinterpret_cast<const float4*>(row);
            float2 v2 = *reinterpret_cast<const float2*>(row + 4);
            PACK2(dup[r][0], v4.x, v4.x);
            PACK2(dup[r][1], v4.y, v4.y);
            PACK2(dup[r][2], v4.z, v4.z);
            PACK2(dup[r][3], v4.w, v4.w);
            PACK2(dup[r][4], v2.x, v2.x);
            PACK2(dup[r][5], v2.y, v2.y);
        }

        const float* wrow = &s_w[ci*9*16 + cg*4];
        #pragma unroll
        for (int p = 0; p < 2; p++) {
            u64 wv[9];
            #pragma unroll
            for (int t = 0; t < 9; t++)
                wv[t] = *reinterpret_cast<const u64*>(&wrow[t*16 + p*2]);
            #pragma unroll
            for (int kh = 0; kh < 3; kh++)
                #pragma unroll
                for (int kw = 0; kw < 3; kw++)
                    #pragma unroll
                    for (int i = 0; i < 2; i++)
                        #pragma unroll
                        for (int j = 0; j < 4; j++)
                            FMA2(acc[p][i][j], dup[i+kh][j+kw], wv[kh*3+kw], acc[p][i][j]);
        }

        #pragma unroll
        for (int k = 0; k < 3; k++) if (act[k])
            s_in[buf ^ 1][dstO[k]] = pre[k];
        __syncthreads();
    }

    #pragma unroll
    for (int p = 0; p < 2; p++) {
        const int co0 = co_base + cg*4 + 2*p;
        const float bv0 = bias[co0], bv1 = bias[co0 + 1];
        float* ob0 = out + (size_t)(b*CH + co0    ) * HW;
        float* ob1 = out + (size_t)(b*CH + co0 + 1) * HW;
        float s0 = 0.f, q0 = 0.f, s1 = 0.f, q1 = 0.f;
        #pragma unroll
        for (int i = 0; i < 2; i++) {
            float lo[4], hi[4];
            #pragma unroll
            for (int j = 0; j < 4; j++) {
                float l, h2;
                UNPK2(l, h2, acc[p][i][j]);
                lo[j] = l + bv0; hi[j] = h2 + bv1;
                s0 += lo[j]; q0 += lo[j]*lo[j];
                s1 += hi[j]; q1 += hi[j]*hi[j];
            }
            *reinterpret_cast<float4*>(&ob0[(h0+i)*W + w0]) = make_float4(lo[0],lo[1],lo[2],lo[3]);
            *reinterpret_cast<float4*>(&ob1[(h0+i)*W + w0]) = make_float4(hi[0],hi[1],hi[2],hi[3]);
        }
        #pragma unroll
        for (int off = 16; off; off >>= 1) {
            s0 += __shfl_down_sync(0xffffffffu, s0, off);
            q0 += __shfl_down_sync(0xffffffffu, q0, off);
            s1 += __shfl_down_sync(0xffffffffu, s1, off);
            q1 += __shfl_down_sync(0xffffffffu, q1, off);
        }
        if ((tid & 31) == 0) {
            atomicAdd(&statacc[(b*CH + co0)*2    ], s0);
            atomicAdd(&statacc[(b*CH + co0)*2 + 1], q0);
            atomicAdd(&statacc[(b*CH + co0+1)*2    ], s1);
            atomicAdd(&statacc[(b*CH + co0+1)*2 + 1], q1);
        }
    }
}

// ---------------- projection conv (64->1) + residual: 16x32 tile, dbl-buffered ----------------
__global__ __launch_bounds__(256)
void proj_kernel(const float* __restrict__ in, const float* __restrict__ rawst,
                 const float* __restrict__ wgt, const float* __restrict__ bias,
                 const float* __restrict__ xIn, float* __restrict__ out)
{
    __shared__ float s_w[64*9];
    __shared__ float2 s_nrm[64];
    __shared__ float s_in[2][18*36];
    const int tid = threadIdx.x;
    const int tileW = blockIdx.x & 7;
    const int tileH = blockIdx.x >> 3;   // 0..15
    const int b = blockIdx.z;

    for (int g = tid; g < 576; g += 256) s_w[g] = wgt[g];
    if (tid < 64) {
        const float inv = 1.f / (float)HW;
        float2 s = ((const float2*)rawst)[b*64 + tid];
        float m = s.x * inv;
        float v = s.y * inv - m*m;
        s_nrm[tid] = make_float2(m, rsqrtf(v + EPS));
    }
    __syncthreads();

    const int pw = tid & 31, hp = tid >> 5;  // w 0..31, hpair 0..7
    const int h0 = tileH*16 + hp*2;
    const int w0 = tileW*32 + pw;
    const int hbase = tileH*16 - 1, wbase = tileW*32 - 1;

    int srcO[3], dstO[3]; bool act[3];
    #pragma unroll
    for (int k = 0; k < 3; k++) {
        int g = tid + k*256;
        act[k] = (g < 612);
        int gg = act[k] ? g : 0;
        int r = gg / 34, c = gg - r*34;
        int gh = hbase + r; gh = gh < 0 ? 0 : (gh > H-1 ? H-1 : gh);
        int gw = wbase + c; gw = gw < 0 ? 0 : (gw > W-1 ? W-1 : gw);
        srcO[k] = gh*W + gw;
        dstO[k] = r*36 + c;
    }

    const float* inb = in + (size_t)b*64*HW;

    {
        float2 mr = s_nrm[0];
        #pragma unroll
        for (int k = 0; k < 3; k++) if (act[k]) {
            float v = inb[srcO[k]];
            v = (v - mr.x) * mr.y;
            v = v >= 0.f ? v : SLOPE * v;
            s_in[0][dstO[k]] = v;
        }
    }
    __syncthreads();

    float acc0 = 0.f, acc1 = 0.f;
    for (int ci = 0; ci < 64; ci++) {
        const int buf = ci & 1;
        const int cn = (ci + 1 < 64) ? ci + 1 : 63;
        float pre[3];
        float2 nmr = s_nrm[cn];
        {
            const float* pn = inb + (size_t)cn*HW;
            #pragma unroll
            for (int k = 0; k < 3; k++) pre[k] = act[k] ? pn[srcO[k]] : 0.f;
        }

        float rr[4][3];
        #pragma unroll
        for (int r = 0; r < 4; r++)
            #pragma unroll
            for (int c = 0; c < 3; c++)
                rr[r][c] = s_in[buf][(hp*2 + r)*36 + pw + c];

        const float* wv = &s_w[ci*9];
        #pragma unroll
        for (int kh = 0; kh < 3; kh++)
            #pragma unroll
            for (int kw = 0; kw < 3; kw++) {
                float wvv = wv[kh*3 + kw];
                acc0 = fmaf(rr[kh    ][kw], wvv, acc0);
                acc1 = fmaf(rr[kh + 1][kw], wvv, acc1);
            }

        #pragma unroll
        for (int k = 0; k < 3; k++) if (act[k]) {
            float v = pre[k];
            v = (v - nmr.x) * nmr.y;
            v = v >= 0.f ? v : SLOPE * v;
            s_in[buf ^ 1][dstO[k]] = v;
        }
        __syncthreads();
    }

    int idx = b*HW + h0*W + w0;
    out[idx]     = acc0 + bias[0] + xIn[idx];
    out[idx + W] = acc1 + bias[0] + xIn[idx + W];
}

// ---------------- shift-search loss: streaming partials ----------------
__global__ __launch_bounds__(256)
void loss_part_kernel(const float* __restrict__ hr, const float* __restrict__ tgt)
{
    const int sy = blockIdx.x, rc = blockIdx.y, b = blockIdx.z;
    const int tid = threadIdx.x;
    const int lane = tid & 31;
    __shared__ float s_hr[2][256];
    __shared__ float s_t[2][244];

    const float* hp = hr  + (size_t)b*HW;
    const float* tp = tgt + (size_t)b*HW;
    const int r0 = rc*61;

    float X[13], S1[13], S2[13];
    #pragma unroll
    for (int s = 0; s < 13; s++) { X[s] = 0.f; S1[s] = 0.f; S2[s] = 0.f; }
    float t1 = 0.f, t2 = 0.f;

    s_hr[0][tid] = hp[(sy + r0)*W + tid];
    if (tid < CROP) s_t[0][tid] = tp[(6 + r0)*W + 6 + tid];
    __syncthreads();

    for (int r = 0; r < 61; r++) {
        const int buf = r & 1;
        float hv = 0.f, tv = 0.f;
        if (r < 60) {
            hv = hp[(sy + r0 + r + 1)*W + tid];
            if (tid < CROP) tv = tp[(6 + r0 + r + 1)*W + 6 + tid];
        }
        if (tid < CROP) {
            const float tc = s_t[buf][tid];
            t1 += tc; t2 = fmaf(tc, tc, t2);
            #pragma unroll
            for (int s = 0; s < 13; s++) {
                const float v = s_hr[buf][s + tid];
                X[s]  = fmaf(v, tc, X[s]);
                S1[s] += v;
                S2[s] = fmaf(v, v, S2[s]);
            }
        }
        if (r < 60) {
            s_hr[buf ^ 1][tid] = hv;
            if (tid < CROP) s_t[buf ^ 1][tid] = tv;
        }
        __syncthreads();
    }

    float* part = g_loss_part + ((size_t)(b*13 + sy))*13*3;
    #pragma unroll
    for (int s = 0; s < 13; s++) {
        float x = X[s], a = S1[s], q = S2[s];
        #pragma unroll
        for (int off = 16; off; off >>= 1) {
            x += __shfl_down_sync(0xffffffffu, x, off);
            a += __shfl_down_sync(0xffffffffu, a, off);
            q += __shfl_down_sync(0xffffffffu, q, off);
        }
        if (lane == 0) {
            atomicAdd(&part[s*3    ], x);
            atomicAdd(&part[s*3 + 1], a);
            atomicAdd(&part[s*3 + 2], q);
        }
    }
    if (sy == 0) {
        #pragma unroll
        for (int off = 16; off; off >>= 1) {
            t1 += __shfl_down_sync(0xffffffffu, t1, off);
            t2 += __shfl_down_sync(0xffffffffu, t2, off);
        }
        if (lane == 0) {
            atomicAdd(&g_loss_t[b*2    ], t1);
            atomicAdd(&g_loss_t[b*2 + 1], t2);
        }
    }
}

__global__ __launch_bounds__(256)
void loss_final_kernel(float* __restrict__ outp) {
    __shared__ float mn[256];
    const float invN = 1.f / ((float)CROP * (float)CROP);
    float total = 0.f;
    for (int b = 0; b < BSZ; b++) {
        float v = 1e30f;
        if (threadIdx.x < 169) {
            const float* part = g_loss_part + ((size_t)b*169 + threadIdx.x)*3;
            const float Xv = part[0], S1 = part[1], S2 = part[2];
            const float T1 = g_loss_t[b*2], T2 = g_loss_t[b*2 + 1];
            const float e2 = (S2 - 2.f*Xv + T2) * invN;
            const float e1 = (S1 - T1) * invN;
            v = e2 - e1*e1;
        }
        mn[threadIdx.x] = v;
        __syncthreads();
        for (int off = 128; off; off >>= 1) {
            if (threadIdx.x < off) mn[threadIdx.x] = fminf(mn[threadIdx.x], mn[threadIdx.x + off]);
            __syncthreads();
        }
        if (threadIdx.x == 0) total += mn[0];
        __syncthreads();
    }
    if (threadIdx.x == 0) outp[0] = total * (1.f / BSZ);
}

// ---------------- launch ----------------
extern "C" void kernel_launch(void* const* d_in, const int* in_sizes, int n_in,
                              void* d_out, int out_size)
{
    const float* xIn    = (const float*)d_in[0];
    const float* target = (const float*)d_in[1];
    const float* w0     = (const float*)d_in[2];
    const float* b0     = (const float*)d_in[3];
    const float* ws     = (const float*)d_in[4];
    const float* bs     = (const float*)d_in[5];
    const float* wp     = (const float*)d_in[6];
    const float* bp     = (const float*)d_in[7];
    float* out = (float*)d_out;

    static int attr_done = 0;
    if (!attr_done) {
        cudaFuncSetAttribute(mma_conv_kernel, cudaFuncAttributeMaxDynamicSharedMemorySize, SMEM_MMA);
        attr_done = 1;
    }

    float *actA, *actB, *stats;
    __half* wprep;
    cudaGetSymbolAddress((void**)&actA,  g_actA);
    cudaGetSymbolAddress((void**)&actB,  g_actB);
    cudaGetSymbolAddress((void**)&stats, g_stats);
    cudaGetSymbolAddress((void**)&wprep, g_wprep);

    // launch 1: weight prep + accumulator zeroing
    wprep_kernel<<<dim3(9, 7), 256>>>(ws);

    // launch 2: layer 0 (1 -> 64) scalar path, raw stats -> slot 0
    conv_kernel<<<dim3(128, 4, BSZ), 256>>>(xIn, w0, b0, actA, stats, 1);

    const float* cur = actA;
    float* nxt = actB;
    for (int i = 0; i < 7; i++) {
        mma_conv_kernel<<<dim3(8, 32, BSZ), 256, SMEM_MMA>>>(
            cur, wprep + (size_t)i*18*4096, bs + i*64,
            stats + (size_t)i*BSZ*CH*2, nxt, stats + (size_t)(i+1)*BSZ*CH*2);
        float* tmp = (float*)cur; cur = nxt; nxt = tmp;
    }

    proj_kernel<<<dim3(128, 1, BSZ), 256>>>(cur, stats + (size_t)7*BSZ*CH*2,
                                            wp, bp, xIn, out);
    loss_part_kernel<<<dim3(13, 4, BSZ), 256>>>(out, target);
    loss_final_kernel<<<1, 256>>>(out + (out_size - 1));
}